// round 3
// baseline (speedup 1.0000x reference)
#include <cuda_runtime.h>

// out[b, i] = cos(theta_i) * ( sum_k sign_i(k) * x[b,k]^2 ) / ( sum_k x[b,k]^2 )
//
// Derivation: psi = x/||x|| is real. RX(t)^dag Z RX(t) = cos(t) Z + sin(t) Y,
// and <Y> = 0 for any real state. Gates on other wires conjugate to identity.
// sign_i(k) = +1 if bit (3-i) of k (MSB-first wire order) is 0, else -1.
//
// 2 samples per thread, all 8 LDG.128 front-batched (MLP_p1 = 8).

__device__ __forceinline__ float4 sample_out(
    const float4 v0, const float4 v1, const float4 v2, const float4 v3,
    float c0, float c1, float c2, float c3)
{
    float p0  = v0.x * v0.x, p1  = v0.y * v0.y, p2  = v0.z * v0.z, p3  = v0.w * v0.w;
    float p4  = v1.x * v1.x, p5  = v1.y * v1.y, p6  = v1.z * v1.z, p7  = v1.w * v1.w;
    float p8  = v2.x * v2.x, p9  = v2.y * v2.y, p10 = v2.z * v2.z, p11 = v2.w * v2.w;
    float p12 = v3.x * v3.x, p13 = v3.y * v3.y, p14 = v3.z * v3.z, p15 = v3.w * v3.w;

    float q0 = (p0  + p1)  + (p2  + p3);
    float q1 = (p4  + p5)  + (p6  + p7);
    float q2 = (p8  + p9)  + (p10 + p11);
    float q3 = (p12 + p13) + (p14 + p15);

    float tot = (q0 + q1) + (q2 + q3);

    float z0 = (q0 + q1) - (q2 + q3);                       // bit3
    float z1 = (q0 - q1) + (q2 - q3);                       // bit2
    float z2 = ((p0 + p1) - (p2 + p3)) + ((p4 + p5) - (p6 + p7))
             + ((p8 + p9) - (p10 + p11)) + ((p12 + p13) - (p14 + p15));  // bit1
    float z3 = ((p0 - p1) + (p2 - p3)) + ((p4 - p5) + (p6 - p7))
             + ((p8 - p9) + (p10 - p11)) + ((p12 - p13) + (p14 - p15)); // bit0

    float inv = __frcp_rn(tot);
    return make_float4(c0 * z0 * inv, c1 * z1 * inv, c2 * z2 * inv, c3 * z3 * inv);
}

__global__ __launch_bounds__(256)
void quantum_layer_kernel(const float4* __restrict__ x4,
                          const float* __restrict__ qw,
                          float4* __restrict__ out,
                          int B) {
    const float c0 = __cosf(qw[0]);
    const float c1 = __cosf(qw[1]);
    const float c2 = __cosf(qw[2]);
    const float c3 = __cosf(qw[3]);

    // Thread t handles samples 2t and 2t+1 (adjacent -> coalesced loads+stores).
    int b0 = (blockIdx.x * blockDim.x + threadIdx.x) * 2;
    if (b0 + 1 < B) {
        // Front-batch all 8 x LDG.128
        const float4 a0 = x4[b0 * 4 + 0];
        const float4 a1 = x4[b0 * 4 + 1];
        const float4 a2 = x4[b0 * 4 + 2];
        const float4 a3 = x4[b0 * 4 + 3];
        const float4 b0v = x4[b0 * 4 + 4];
        const float4 b1v = x4[b0 * 4 + 5];
        const float4 b2v = x4[b0 * 4 + 6];
        const float4 b3v = x4[b0 * 4 + 7];

        out[b0]     = sample_out(a0, a1, a2, a3, c0, c1, c2, c3);
        out[b0 + 1] = sample_out(b0v, b1v, b2v, b3v, c0, c1, c2, c3);
    } else if (b0 < B) {
        const float4 a0 = x4[b0 * 4 + 0];
        const float4 a1 = x4[b0 * 4 + 1];
        const float4 a2 = x4[b0 * 4 + 2];
        const float4 a3 = x4[b0 * 4 + 3];
        out[b0] = sample_out(a0, a1, a2, a3, c0, c1, c2, c3);
    }
}

extern "C" void kernel_launch(void* const* d_in, const int* in_sizes, int n_in,
                              void* d_out, int out_size) {
    const float4* x4 = (const float4*)d_in[0];   // x: [B, 16] float32
    const float*  qw = (const float*)d_in[1];    // q_weights: [4] float32
    float4* out = (float4*)d_out;                // out: [B, 4] float32

    int B = in_sizes[0] / 16;
    int threads = 256;
    int samples_per_block = threads * 2;
    int blocks = (B + samples_per_block - 1) / samples_per_block;
    quantum_layer_kernel<<<blocks, threads>>>(x4, qw, out, B);
}

// round 13
// speedup vs baseline: 1.0214x; 1.0214x over previous
#include <cuda_runtime.h>

// out[b, i] = cos(theta_i) * ( sum_k sign_i(k) * x[b,k]^2 ) / ( sum_k x[b,k]^2 )
//
// Derivation: psi = x/||x|| is real. RX(t)^dag Z RX(t) = cos(t) Z + sin(t) Y,
// and <Y> = 0 for any real state. Gates on other wires conjugate to identity.
// sign_i(k) = +1 if bit (3-i) of k (MSB-first wire order) is 0, else -1.
//
// 2 samples per thread, 8 front-batched LDG.128 with .cs (evict-streaming) —
// data has zero reuse, so L1 allocation is pure overhead (L1 was 83% in R3).

__device__ __forceinline__ float4 sample_out(
    const float4 v0, const float4 v1, const float4 v2, const float4 v3,
    float c0, float c1, float c2, float c3)
{
    float p0  = v0.x * v0.x, p1  = v0.y * v0.y, p2  = v0.z * v0.z, p3  = v0.w * v0.w;
    float p4  = v1.x * v1.x, p5  = v1.y * v1.y, p6  = v1.z * v1.z, p7  = v1.w * v1.w;
    float p8  = v2.x * v2.x, p9  = v2.y * v2.y, p10 = v2.z * v2.z, p11 = v2.w * v2.w;
    float p12 = v3.x * v3.x, p13 = v3.y * v3.y, p14 = v3.z * v3.z, p15 = v3.w * v3.w;

    float q0 = (p0  + p1)  + (p2  + p3);
    float q1 = (p4  + p5)  + (p6  + p7);
    float q2 = (p8  + p9)  + (p10 + p11);
    float q3 = (p12 + p13) + (p14 + p15);

    float tot = (q0 + q1) + (q2 + q3);

    float z0 = (q0 + q1) - (q2 + q3);                       // bit3
    float z1 = (q0 - q1) + (q2 - q3);                       // bit2
    float z2 = ((p0 + p1) - (p2 + p3)) + ((p4 + p5) - (p6 + p7))
             + ((p8 + p9) - (p10 + p11)) + ((p12 + p13) - (p14 + p15));  // bit1
    float z3 = ((p0 - p1) + (p2 - p3)) + ((p4 - p5) + (p6 - p7))
             + ((p8 - p9) + (p10 - p11)) + ((p12 - p13) + (p14 - p15)); // bit0

    float inv = __frcp_rn(tot);
    return make_float4(c0 * z0 * inv, c1 * z1 * inv, c2 * z2 * inv, c3 * z3 * inv);
}

__global__ __launch_bounds__(256)
void quantum_layer_kernel(const float4* __restrict__ x4,
                          const float* __restrict__ qw,
                          float4* __restrict__ out,
                          int B) {
    const float c0 = __cosf(qw[0]);
    const float c1 = __cosf(qw[1]);
    const float c2 = __cosf(qw[2]);
    const float c3 = __cosf(qw[3]);

    // Thread t handles samples 2t and 2t+1 (adjacent -> coalesced loads+stores).
    int b0 = (blockIdx.x * blockDim.x + threadIdx.x) * 2;
    const float4* p = x4 + (size_t)b0 * 4;

    if (b0 + 1 < B) {
        // Front-batch all 8 x LDG.128.CS (streaming, no L1 allocate)
        const float4 a0 = __ldcs(p + 0);
        const float4 a1 = __ldcs(p + 1);
        const float4 a2 = __ldcs(p + 2);
        const float4 a3 = __ldcs(p + 3);
        const float4 b0v = __ldcs(p + 4);
        const float4 b1v = __ldcs(p + 5);
        const float4 b2v = __ldcs(p + 6);
        const float4 b3v = __ldcs(p + 7);

        float4 o0 = sample_out(a0, a1, a2, a3, c0, c1, c2, c3);
        float4 o1 = sample_out(b0v, b1v, b2v, b3v, c0, c1, c2, c3);
        __stcs(out + b0, o0);
        __stcs(out + b0 + 1, o1);
    } else if (b0 < B) {
        const float4 a0 = __ldcs(p + 0);
        const float4 a1 = __ldcs(p + 1);
        const float4 a2 = __ldcs(p + 2);
        const float4 a3 = __ldcs(p + 3);
        float4 o0 = sample_out(a0, a1, a2, a3, c0, c1, c2, c3);
        __stcs(out + b0, o0);
    }
}

extern "C" void kernel_launch(void* const* d_in, const int* in_sizes, int n_in,
                              void* d_out, int out_size) {
    const float4* x4 = (const float4*)d_in[0];   // x: [B, 16] float32
    const float*  qw = (const float*)d_in[1];    // q_weights: [4] float32
    float4* out = (float4*)d_out;                // out: [B, 4] float32

    int B = in_sizes[0] / 16;
    int threads = 256;
    int samples_per_block = threads * 2;
    int blocks = (B + samples_per_block - 1) / samples_per_block;
    quantum_layer_kernel<<<blocks, threads>>>(x4, qw, out, B);
}